// round 10
// baseline (speedup 1.0000x reference)
#include <cuda_runtime.h>
#include <cuda_fp16.h>
#include <cstdint>

// ---------------- problem constants ----------------
#define E_      8
#define D_      64
#define H_      512
#define B_      32768
#define IN_RAW  67
#define BM      64
#define HSTR    520
#define THREADS 1024

// SMEM layout (bytes)
#define NSLOT     4
#define BSLOT     32768
#define SM_H      (NSLOT * BSLOT)        // 131072
#define SM_MBAR   (SM_H + 66560)         // full[4] @ +0, empty[4] @ +32
#define SM_TOTAL  (SM_MBAR + 64)

#define NCHUNKS 42            // 2 (L1) + 16 (L2) + 16 (L3) + 8 (L4)

// ---------------- device scratch ----------------
__device__ float g_dyn[(size_t)E_ * B_ * D_];
__device__ float g_b1eff[E_ * H_];
__device__ __align__(128) char g_w1s[E_ * 2 * 32768];
__device__ __align__(128) char g_w2s[(size_t)E_ * 16 * 32768];
__device__ __align__(128) char g_w3s[(size_t)E_ * 16 * 32768];
__device__ __align__(128) char g_w4s[E_ * 8 * 8192];

// ---------------- low-level helpers ----------------
__device__ __forceinline__ uint32_t smem_u32(const void* p) {
    uint32_t a;
    asm("{ .reg .u64 t; cvta.to.shared.u64 t, %1; cvt.u32.u64 %0, t; }" : "=r"(a) : "l"(p));
    return a;
}
__device__ __forceinline__ void ldsm4(uint32_t* r, const void* p) {
    asm volatile("ldmatrix.sync.aligned.m8n8.x4.shared.b16 {%0,%1,%2,%3}, [%4];"
        : "=r"(r[0]), "=r"(r[1]), "=r"(r[2]), "=r"(r[3]) : "r"(smem_u32(p)));
}
__device__ __forceinline__ void ldsm2(uint32_t& r0, uint32_t& r1, const void* p) {
    asm volatile("ldmatrix.sync.aligned.m8n8.x2.shared.b16 {%0,%1}, [%2];"
        : "=r"(r0), "=r"(r1) : "r"(smem_u32(p)));
}
__device__ __forceinline__ void mma16816(float* c, const uint32_t* a, uint32_t b0, uint32_t b1) {
    asm volatile(
        "mma.sync.aligned.m16n8k16.row.col.f32.f16.f16.f32 "
        "{%0,%1,%2,%3}, {%4,%5,%6,%7}, {%8,%9}, {%0,%1,%2,%3};"
        : "+f"(c[0]), "+f"(c[1]), "+f"(c[2]), "+f"(c[3])
        : "r"(a[0]), "r"(a[1]), "r"(a[2]), "r"(a[3]), "r"(b0), "r"(b1));
}
__device__ __forceinline__ void mbar_init(uint32_t a, uint32_t c) {
    asm volatile("mbarrier.init.shared.b64 [%0], %1;" :: "r"(a), "r"(c) : "memory");
}
__device__ __forceinline__ void mbar_arrive(uint32_t a) {
    asm volatile("mbarrier.arrive.shared.b64 _, [%0];" :: "r"(a) : "memory");
}
__device__ __forceinline__ void mbar_expect_tx(uint32_t a, uint32_t bytes) {
    asm volatile("mbarrier.arrive.expect_tx.shared.b64 _, [%0], %1;" :: "r"(a), "r"(bytes) : "memory");
}
__device__ __forceinline__ void bulk_g2s(uint32_t sdst, const void* gsrc, uint32_t bytes, uint32_t mbar) {
    asm volatile(
        "cp.async.bulk.shared::cluster.global.mbarrier::complete_tx::bytes [%0], [%1], %2, [%3];"
        :: "r"(sdst), "l"(gsrc), "r"(bytes), "r"(mbar) : "memory");
}
__device__ __forceinline__ void mbar_wait(uint32_t mbar, uint32_t parity) {
    uint32_t done;
    asm volatile(
        "{ .reg .pred p; mbarrier.try_wait.parity.acquire.cta.shared::cta.b64 p, [%1], %2; selp.b32 %0, 1, 0, p; }"
        : "=r"(done) : "r"(mbar), "r"(parity) : "memory");
    if (!done) {
        asm volatile(
            "{ .reg .pred P1;\n"
            "W_%=:\n\t"
            "mbarrier.try_wait.parity.acquire.cta.shared::cta.b64 P1, [%0], %1, 0x989680;\n\t"
            "@P1 bra.uni D_%=;\n\t"
            "bra.uni W_%=;\n"
            "D_%=: }"
            :: "r"(mbar), "r"(parity) : "memory");
    }
}
__device__ __forceinline__ float tanh_fast(float x) {
    float y;
    asm("tanh.approx.f32 %0, %1;" : "=f"(y) : "f"(x));
    return y;
}

// ---------------- weight prep ----------------
__global__ void conv_small(const float* __restrict__ W1, const float* __restrict__ W4,
                           const float* __restrict__ b1, const float* __restrict__ t,
                           const float* __restrict__ omega)
{
    int i = blockIdx.x * blockDim.x + threadIdx.x;
    if (i < 131072) {
        int e = i >> 14, r = i & 16383;
        int n = r >> 5, k = (r & 31) * 2;
        int kc = k >> 5, kl = k & 31, j = kl >> 3;
        size_t chunk = (size_t)(e * 2 + kc) * 32768;
        uint32_t off = (uint32_t)((n >> 1) * 128 + (n & 1) * 64
                     + ((j ^ ((n >> 1) & 3)) << 4) + (kl & 7) * 2);
        const float* s = W1 + ((size_t)e * 512 + n) * IN_RAW + k;
        *(__half2*)(g_w1s + chunk + off) = __floats2half2_rn(s[0], s[1]);
    } else if (i < 262144) {
        int jj = i - 131072;
        int e = jj >> 14, r = jj & 16383;
        int n = r >> 8, k = (r & 255) * 2;
        int kc = k >> 6, kl = k & 63;
        size_t chunk = ((size_t)e * 8 + kc) * 8192;
        uint32_t off = (uint32_t)(n * 128) + (((uint32_t)(kl * 2)) ^ ((uint32_t)(n & 7) << 4));
        const float* s = W4 + ((size_t)e * 64 + n) * 512 + k;
        *(__half2*)(g_w4s + chunk + off) = __floats2half2_rn(s[0], s[1]);
    } else if (i < 262144 + E_ * H_) {
        int jj = i - 262144;
        int e = jj >> 9;
        float tv = t[0], om = omega[e];
        const float* w = W1 + (size_t)jj * IN_RAW;
        g_b1eff[jj] = b1[jj] + tv * w[64] + sinf(om * tv) * w[65] + cosf(om * tv) * w[66];
    }
}
__global__ void conv_w23s(const float* __restrict__ W, char* __restrict__ dst) {
    int i = blockIdx.x * blockDim.x + threadIdx.x;
    int e = i >> 17, r = i & 131071;
    int n = r >> 8, k = (r & 255) * 2;
    int kc = k >> 5, kl = k & 31, j = kl >> 3;
    size_t chunk = ((size_t)(e * 16 + kc)) * 32768;
    uint32_t off = (uint32_t)((n >> 1) * 128 + (n & 1) * 64
                 + ((j ^ ((n >> 1) & 3)) << 4) + (kl & 7) * 2);
    const float* s = W + ((size_t)e * 512 + n) * 512 + k;
    *(__half2*)(dst + chunk + off) = __floats2half2_rn(s[0], s[1]);
}

// ---------------- 4-slot chunk ring (parity derived from counters) ----------------
struct Stream {
    uint32_t mb;       // full[s] = mb+8s, empty[s] = mb+32+8s
    uint32_t bdst0;
    int gp, gc;
    bool leader;
    const char *w1b, *w2b, *w3b, *w4b;
};
__device__ __forceinline__ void produce_next(Stream& s) {
    int i = s.gp;
    if (i >= NCHUNKS) return;
    if (s.leader) {
        int slot = i & (NSLOT - 1);
        const char* p;
        uint32_t bytes;
        if (i < 2)       { p = s.w1b + (size_t)i * 32768;        bytes = 32768; }
        else if (i < 18) { p = s.w2b + (size_t)(i - 2) * 32768;  bytes = 32768; }
        else if (i < 34) { p = s.w3b + (size_t)(i - 18) * 32768; bytes = 32768; }
        else             { p = s.w4b + (size_t)(i - 34) * 8192;  bytes = 8192;  }
        if (i >= NSLOT) mbar_wait(s.mb + 32 + 8 * slot, (uint32_t)(((i >> 2) & 1) ^ 1));
        mbar_expect_tx(s.mb + 8 * slot, bytes);
        bulk_g2s(s.bdst0 + slot * BSLOT, p, bytes, s.mb + 8 * slot);
    }
    s.gp++;
}
__device__ __forceinline__ int consume_wait(Stream& s) {
    int slot = s.gc & (NSLOT - 1);
    mbar_wait(s.mb + 8 * slot, (uint32_t)((s.gc >> 2) & 1));
    return slot;
}
__device__ __forceinline__ void consume_done(Stream& s, bool wl) {
    if (wl) mbar_arrive(s.mb + 32 + 8 * (s.gc & (NSLOT - 1)));
    s.gc++;
}

// ---------------- N=512 pass (layers 1-3): 32 warps, warp tile 32x32, in-place h ----------------
__device__ __forceinline__ void run_pass512(Stream& S, char* smc, __half* __restrict__ h,
        int nch, const float* __restrict__ bias, int warp, int lane)
{
    const int mg = warp >> 4, ng = warp & 15;
    const bool wl = (lane == 0);
    const int g = lane >> 3, lr = lane & 7;
    const int nbase = ng * 32 + ((g >> 1) << 3) + lr;
    const int jpar = g & 1;

    const __half* abase = h + (mg * 32 + (lane & 15)) * HSTR + ((lane >> 4) << 3);
    uint32_t boff[2][2];
    #pragma unroll
    for (int ks = 0; ks < 2; ks++) {
        const int j = ks * 2 + jpar;
        #pragma unroll
        for (int nt2 = 0; nt2 < 2; nt2++) {
            const int nrow = nbase + nt2 * 16;
            boff[ks][nt2] = (uint32_t)((nrow >> 1) * 128 + (nrow & 1) * 64
                           + ((j ^ ((nrow >> 1) & 3)) << 4));
        }
    }

    float acc[2][4][4];
    #pragma unroll
    for (int mt = 0; mt < 2; mt++)
        #pragma unroll
        for (int nt = 0; nt < 4; nt++)
            #pragma unroll
            for (int i = 0; i < 4; i++) acc[mt][nt][i] = 0.0f;

    #pragma unroll 1
    for (int kc = 0; kc < nch; kc++) {
        int slot = consume_wait(S);
        const char* wb = smc + slot * BSLOT;
        #pragma unroll
        for (int ks = 0; ks < 2; ks++) {
            const int kk = kc * 32 + ks * 16;
            uint32_t a[2][4];
            ldsm4(a[0], abase + kk);
            ldsm4(a[1], abase + 16 * HSTR + kk);
            #pragma unroll
            for (int nt2 = 0; nt2 < 2; nt2++) {
                uint32_t bb[4];
                ldsm4(bb, wb + boff[ks][nt2]);
                mma16816(acc[0][2 * nt2],     a[0], bb[0], bb[1]);
                mma16816(acc[1][2 * nt2],     a[1], bb[0], bb[1]);
                mma16816(acc[0][2 * nt2 + 1], a[0], bb[2], bb[3]);
                mma16816(acc[1][2 * nt2 + 1], a[1], bb[2], bb[3]);
            }
        }
        consume_done(S, wl);
        produce_next(S);
    }

    __syncthreads();   // all reads of h done -> safe to overwrite in place

    #pragma unroll
    for (int mt = 0; mt < 2; mt++) {
        #pragma unroll
        for (int nt = 0; nt < 4; nt++) {
            const int cb = ng * 32 + nt * 8 + (lane & 3) * 2;
            const float2 bb = *(const float2*)(bias + cb);
            const int r0 = mg * 32 + mt * 16 + (lane >> 2);
            float v0 = tanh_fast(acc[mt][nt][0] + bb.x);
            float v1 = tanh_fast(acc[mt][nt][1] + bb.y);
            float v2 = tanh_fast(acc[mt][nt][2] + bb.x);
            float v3 = tanh_fast(acc[mt][nt][3] + bb.y);
            *(__half2*)(h + r0 * HSTR + cb)       = __floats2half2_rn(v0, v1);
            *(__half2*)(h + (r0 + 8) * HSTR + cb) = __floats2half2_rn(v2, v3);
        }
    }
    __syncthreads();   // publish new h before next layer
}

// ---------------- layer 4: N=64 (warps 0-15 compute; 16-31 barrier-only) ----------------
__device__ __forceinline__ void run_pass64(Stream& S, char* smc,
        const __half* __restrict__ h, float* __restrict__ dynout,
        int nch, const float* __restrict__ bias, int warp, int lane)
{
    const bool wl = (lane == 0);
    if (warp < 16) {
        const int mg = warp >> 3, ng = warp & 7;
        const int g = lane >> 3, lr = lane & 7;
        const __half* abase = h + (mg * 32 + (lane & 15)) * HSTR + ((lane >> 4) << 3);
        const int nrow = ng * 8 + lr;

        uint32_t boff[4];
        #pragma unroll
        for (int ks = 0; ks < 4; ks++) {
            const uint32_t j = (uint32_t)(ks * 2 + (g & 1));
            boff[ks] = (uint32_t)(nrow * 128) + ((j << 4) ^ ((uint32_t)(nrow & 7) << 4));
        }

        float acc[2][4];
        #pragma unroll
        for (int mt = 0; mt < 2; mt++)
            #pragma unroll
            for (int i = 0; i < 4; i++) acc[mt][i] = 0.0f;

        #pragma unroll 1
        for (int kc = 0; kc < nch; kc++) {
            int slot = consume_wait(S);
            const char* wb = smc + slot * BSLOT;
            #pragma unroll
            for (int ks = 0; ks < 4; ks++) {
                const int kk = kc * 64 + ks * 16;
                uint32_t a[2][4];
                ldsm4(a[0], abase + kk);
                ldsm4(a[1], abase + 16 * HSTR + kk);
                uint32_t b0, b1;
                ldsm2(b0, b1, wb + boff[ks]);
                mma16816(acc[0], a[0], b0, b1);
                mma16816(acc[1], a[1], b0, b1);
            }
            consume_done(S, wl);
            produce_next(S);     // REQUIRED: chunks 38..41 are produced here
        }

        const int cb = ng * 8 + (lane & 3) * 2;
        const float2 bb = *(const float2*)(bias + cb);
        #pragma unroll
        for (int mt = 0; mt < 2; mt++) {
            const int r0 = mg * 32 + mt * 16 + (lane >> 2);
            float2 f01; f01.x = acc[mt][0] + bb.x; f01.y = acc[mt][1] + bb.y;
            float2 f23; f23.x = acc[mt][2] + bb.x; f23.y = acc[mt][3] + bb.y;
            *(float2*)(dynout + (size_t)r0 * D_ + cb)       = f01;
            *(float2*)(dynout + (size_t)(r0 + 8) * D_ + cb) = f23;
        }
    } else {
        // barrier-only participation
        #pragma unroll 1
        for (int kc = 0; kc < nch; kc++) {
            consume_wait(S);
            consume_done(S, wl);
            produce_next(S);     // keep counters aligned (no-op for non-leader)
        }
    }
}

// ---------------- fused per-tile, per-expert MLP kernel ----------------
__global__ __launch_bounds__(THREADS, 1)
void mlp_kernel(const float* __restrict__ x,
                const float* __restrict__ b2, const float* __restrict__ b3,
                const float* __restrict__ b4)
{
    extern __shared__ __align__(1024) char smc[];
    __half* h = (__half*)(smc + SM_H);
    const uint32_t mb = smem_u32(smc + SM_MBAR);

    const int tid  = threadIdx.x;
    const int warp = tid >> 5, lane = tid & 31;
    const int e    = blockIdx.y;
    const int row0 = blockIdx.x * BM;

    Stream S;
    S.mb = mb;
    S.bdst0 = smem_u32(smc);
    S.gp = 0; S.gc = 0;
    S.leader = (tid == 0);
    S.w1b = g_w1s + (size_t)e * 2 * 32768;
    S.w2b = g_w2s + (size_t)e * 16 * 32768;
    S.w3b = g_w3s + (size_t)e * 16 * 32768;
    S.w4b = g_w4s + (size_t)e * 8 * 8192;

    if (tid == 0) {
        #pragma unroll
        for (int i = 0; i < NSLOT; i++) {
            mbar_init(mb + 8 * i, 1);
            mbar_init(mb + 32 + 8 * i, 32);
        }
        asm volatile("fence.proxy.async.shared::cta;" ::: "memory");
    }
    __syncthreads();

    produce_next(S); produce_next(S); produce_next(S); produce_next(S);

    for (int idx = tid; idx < BM * 64; idx += THREADS) {
        int r = idx >> 6, c = idx & 63;
        h[r * HSTR + c] = __float2half(x[(size_t)(row0 + r) * 64 + c]);
    }
    __syncthreads();

    float* dyn = g_dyn + ((size_t)e * B_ + row0) * D_;

    run_pass512(S, smc, h, 2,  g_b1eff + e * H_, warp, lane);
    run_pass512(S, smc, h, 16, b2 + e * H_,      warp, lane);
    run_pass512(S, smc, h, 16, b3 + e * H_,      warp, lane);
    run_pass64 (S, smc, h, dyn, 8, b4 + e * D_,  warp, lane);
}

// ---------------- expert-weighted combine (deterministic) ----------------
__global__ void combine_k(const float* __restrict__ ew, float* __restrict__ out)
{
    int i = blockIdx.x * blockDim.x + threadIdx.x;
    int b = i >> 6;
    float s = 0.0f;
    #pragma unroll
    for (int e = 0; e < E_; e++)
        s += ew[b * E_ + e] * g_dyn[(size_t)e * B_ * D_ + i];
    out[i] = s;
}

// ---------------- launch ----------------
extern "C" void kernel_launch(void* const* d_in, const int* in_sizes, int n_in,
                              void* d_out, int out_size)
{
    const float* t  = (const float*)d_in[0];
    const float* x  = (const float*)d_in[1];
    const float* ew = (const float*)d_in[2];
    const float* om = (const float*)d_in[3];
    const float* W1 = (const float*)d_in[4];
    const float* b1 = (const float*)d_in[5];
    const float* W2 = (const float*)d_in[6];
    const float* b2 = (const float*)d_in[7];
    const float* W3 = (const float*)d_in[8];
    const float* b3 = (const float*)d_in[9];
    const float* W4 = (const float*)d_in[10];
    const float* b4 = (const float*)d_in[11];
    float* out = (float*)d_out;

    cudaFuncSetAttribute(mlp_kernel, cudaFuncAttributeMaxDynamicSharedMemorySize, SM_TOTAL);

    char* w2s_ptr = nullptr;
    char* w3s_ptr = nullptr;
    cudaGetSymbolAddress((void**)&w2s_ptr, g_w2s);
    cudaGetSymbolAddress((void**)&w3s_ptr, g_w3s);

    // launch order keeps mlp_kernel as the ncu capture target
    conv_small<<<(262144 + E_ * H_ + 255) / 256, 256>>>(W1, W4, b1, t, om);
    conv_w23s<<<(E_ * 512 * 256) / 256, 256>>>(W2, w2s_ptr);
    conv_w23s<<<(E_ * 512 * 256) / 256, 256>>>(W3, w3s_ptr);

    dim3 grid(B_ / BM, E_);
    mlp_kernel<<<grid, THREADS, SM_TOTAL>>>(x, b2, b3, b4);

    combine_k<<<(B_ * D_) / 256, 256>>>(ew, out);
}

// round 11
// speedup vs baseline: 1.2566x; 1.2566x over previous
#include <cuda_runtime.h>
#include <cuda_fp16.h>
#include <cstdint>

// ---------------- problem constants ----------------
#define E_      8
#define D_      64
#define H_      512
#define B_      32768
#define IN_RAW  67
#define BM      64
#define HSTR    520           // halves; row pitch 1040 B
#define THREADS 512

// SMEM layout (bytes)
#define NSLOT     4
#define BSLOT     32768
#define SM_H      (NSLOT * BSLOT)        // 131072
#define SM_MBAR   (SM_H + 66560)         // full[4] @ +0, empty[4] @ +32
#define SM_TOTAL  (SM_MBAR + 64)

#define NCHUNKS 42            // 2 (L1) + 16 (L2) + 16 (L3) + 8 (L4)
#define EBYTES  1179648       // per-expert weight blob: 34*32768 + 8*8192

// ---------------- device scratch ----------------
__device__ float g_dyn[(size_t)E_ * B_ * D_];
__device__ float g_b1eff[E_ * H_];
// unified per-expert weight blob, chunks in stream order
__device__ __align__(128) char g_wall[(size_t)E_ * EBYTES];

// ---------------- low-level helpers ----------------
__device__ __forceinline__ uint32_t smem_u32(const void* p) {
    uint32_t a;
    asm("{ .reg .u64 t; cvta.to.shared.u64 t, %1; cvt.u32.u64 %0, t; }" : "=r"(a) : "l"(p));
    return a;
}
__device__ __forceinline__ void ldsm4a(uint32_t* r, uint32_t a) {
    asm volatile("ldmatrix.sync.aligned.m8n8.x4.shared.b16 {%0,%1,%2,%3}, [%4];"
        : "=r"(r[0]), "=r"(r[1]), "=r"(r[2]), "=r"(r[3]) : "r"(a));
}
__device__ __forceinline__ void ldsm2a(uint32_t& r0, uint32_t& r1, uint32_t a) {
    asm volatile("ldmatrix.sync.aligned.m8n8.x2.shared.b16 {%0,%1}, [%2];"
        : "=r"(r0), "=r"(r1) : "r"(a));
}
__device__ __forceinline__ void mma16816(float* c, const uint32_t* a, uint32_t b0, uint32_t b1) {
    asm volatile(
        "mma.sync.aligned.m16n8k16.row.col.f32.f16.f16.f32 "
        "{%0,%1,%2,%3}, {%4,%5,%6,%7}, {%8,%9}, {%0,%1,%2,%3};"
        : "+f"(c[0]), "+f"(c[1]), "+f"(c[2]), "+f"(c[3])
        : "r"(a[0]), "r"(a[1]), "r"(a[2]), "r"(a[3]), "r"(b0), "r"(b1));
}
__device__ __forceinline__ void mbar_init(uint32_t a, uint32_t c) {
    asm volatile("mbarrier.init.shared.b64 [%0], %1;" :: "r"(a), "r"(c) : "memory");
}
__device__ __forceinline__ void mbar_arrive(uint32_t a) {
    asm volatile("mbarrier.arrive.shared.b64 _, [%0];" :: "r"(a) : "memory");
}
__device__ __forceinline__ void mbar_expect_tx(uint32_t a, uint32_t bytes) {
    asm volatile("mbarrier.arrive.expect_tx.shared.b64 _, [%0], %1;" :: "r"(a), "r"(bytes) : "memory");
}
__device__ __forceinline__ void bulk_g2s(uint32_t sdst, const void* gsrc, uint32_t bytes, uint32_t mbar) {
    asm volatile(
        "cp.async.bulk.shared::cluster.global.mbarrier::complete_tx::bytes [%0], [%1], %2, [%3];"
        :: "r"(sdst), "l"(gsrc), "r"(bytes), "r"(mbar) : "memory");
}
__device__ __forceinline__ void mbar_wait(uint32_t mbar, uint32_t parity) {
    uint32_t done;
    asm volatile(
        "{ .reg .pred p; mbarrier.try_wait.parity.acquire.cta.shared::cta.b64 p, [%1], %2; selp.b32 %0, 1, 0, p; }"
        : "=r"(done) : "r"(mbar), "r"(parity) : "memory");
    if (!done) {
        asm volatile(
            "{ .reg .pred P1;\n"
            "W_%=:\n\t"
            "mbarrier.try_wait.parity.acquire.cta.shared::cta.b64 P1, [%0], %1, 0x989680;\n\t"
            "@P1 bra.uni D_%=;\n\t"
            "bra.uni W_%=;\n"
            "D_%=: }"
            :: "r"(mbar), "r"(parity) : "memory");
    }
}
__device__ __forceinline__ float tanh_fast(float x) {
    float y;
    asm("tanh.approx.f32 %0, %1;" : "=f"(y) : "f"(x));
    return y;
}

// ---------------- weight prep (into unified blob) ----------------
__global__ void conv_small(const float* __restrict__ W1, const float* __restrict__ W4,
                           const float* __restrict__ b1, const float* __restrict__ t,
                           const float* __restrict__ omega)
{
    int i = blockIdx.x * blockDim.x + threadIdx.x;
    if (i < 131072) {
        // W1[:, :64] -> chunks 0..1
        int e = i >> 14, r = i & 16383;
        int n = r >> 5, k = (r & 31) * 2;
        int kc = k >> 5, kl = k & 31, j = kl >> 3;
        size_t base = (size_t)e * EBYTES + (size_t)kc * 32768;
        uint32_t off = (uint32_t)((n >> 1) * 128 + (n & 1) * 64
                     + ((j ^ ((n >> 1) & 3)) << 4) + (kl & 7) * 2);
        const float* s = W1 + ((size_t)e * 512 + n) * IN_RAW + k;
        *(__half2*)(g_wall + base + off) = __floats2half2_rn(s[0], s[1]);
    } else if (i < 262144) {
        // W4 -> chunks 34..41 (K=64, 128B rows)
        int jj = i - 131072;
        int e = jj >> 14, r = jj & 16383;
        int n = r >> 8, k = (r & 255) * 2;
        int kc = k >> 6, kl = k & 63;
        size_t base = (size_t)e * EBYTES + 34u * 32768 + (size_t)kc * 8192;
        uint32_t off = (uint32_t)(n * 128) + (((uint32_t)(kl * 2)) ^ ((uint32_t)(n & 7) << 4));
        const float* s = W4 + ((size_t)e * 64 + n) * 512 + k;
        *(__half2*)(g_wall + base + off) = __floats2half2_rn(s[0], s[1]);
    } else if (i < 262144 + E_ * H_) {
        int jj = i - 262144;
        int e = jj >> 9;
        float tv = t[0], om = omega[e];
        const float* w = W1 + (size_t)jj * IN_RAW;
        g_b1eff[jj] = b1[jj] + tv * w[64] + sinf(om * tv) * w[65] + cosf(om * tv) * w[66];
    }
}
// W2 -> chunks 2..17 (cbase=2); W3 -> chunks 18..33 (cbase=18)
__global__ void conv_w23s(const float* __restrict__ W, int cbase) {
    int i = blockIdx.x * blockDim.x + threadIdx.x;
    int e = i >> 17, r = i & 131071;
    int n = r >> 8, k = (r & 255) * 2;
    int kc = k >> 5, kl = k & 31, j = kl >> 3;
    size_t base = (size_t)e * EBYTES + (size_t)(cbase + kc) * 32768;
    uint32_t off = (uint32_t)((n >> 1) * 128 + (n & 1) * 64
                 + ((j ^ ((n >> 1) & 3)) << 4) + (kl & 7) * 2);
    const float* s = W + ((size_t)e * 512 + n) * 512 + k;
    *(__half2*)(g_wall + base + off) = __floats2half2_rn(s[0], s[1]);
}

// ---------------- 4-slot chunk ring ----------------
struct Stream {
    uint32_t mb;       // full[s] = mb+8s, empty[s] = mb+32+8s
    uint32_t bdst0;    // smem u32 of slot 0
    int gp, gc;
    bool leader;
    const char* wbase; // per-expert blob base
};
__device__ __forceinline__ void produce_next(Stream& s) {
    int i = s.gp;
    if (i >= NCHUNKS) return;
    if (s.leader) {
        int slot = i & 3;
        uint32_t off, bytes;
        if (i < 34) { off = (uint32_t)i << 15; bytes = 32768u; }
        else        { off = (34u << 15) + ((uint32_t)(i - 34) << 13); bytes = 8192u; }
        if (i >= NSLOT) mbar_wait(s.mb + 32 + 8 * slot, (uint32_t)(((i >> 2) & 1) ^ 1));
        mbar_expect_tx(s.mb + 8 * slot, bytes);
        bulk_g2s(s.bdst0 + slot * BSLOT, s.wbase + off, bytes, s.mb + 8 * slot);
    }
    s.gp++;
}
// wait for chunk idx full; return smem u32 base of its slot
__device__ __forceinline__ uint32_t slot_wait(Stream& s, int idx) {
    int slot = idx & 3;
    mbar_wait(s.mb + 8 * slot, (uint32_t)((idx >> 2) & 1));
    return s.bdst0 + (uint32_t)slot * BSLOT;
}
__device__ __forceinline__ void consume_done(Stream& s, bool wl) {
    if (wl) mbar_arrive(s.mb + 32 + 8 * (s.gc & 3));
    s.gc++;
}

// ---------------- fragment ops ----------------
__device__ __forceinline__ void load_A(uint32_t* a, uint32_t addr) {
    ldsm4a(a,     addr);
    ldsm4a(a + 4, addr + 16 * 1040);
}
__device__ __forceinline__ void load_B(uint32_t* b, uint32_t wb, const uint32_t* boff, uint32_t x) {
    ldsm4a(b,      wb + (boff[0] ^ x));
    ldsm4a(b + 4,  wb + (boff[1] ^ x));
    ldsm4a(b + 8,  wb + (boff[2] ^ x));
    ldsm4a(b + 12, wb + (boff[3] ^ x));
}
__device__ __forceinline__ void mma_batch(float (&acc)[2][8][4], const uint32_t* a, const uint32_t* b) {
    #pragma unroll
    for (int nt4 = 0; nt4 < 4; nt4++) {
        mma16816(acc[0][2 * nt4],     a,     b[4 * nt4],     b[4 * nt4 + 1]);
        mma16816(acc[1][2 * nt4],     a + 4, b[4 * nt4],     b[4 * nt4 + 1]);
        mma16816(acc[0][2 * nt4 + 1], a,     b[4 * nt4 + 2], b[4 * nt4 + 3]);
        mma16816(acc[1][2 * nt4 + 1], a + 4, b[4 * nt4 + 2], b[4 * nt4 + 3]);
    }
}

// ---------------- N=512 pass (layers 1-3): 16 warps, tile 32x64, pipelined ----------------
__device__ __forceinline__ void run_pass512(Stream& S, __half* __restrict__ h, uint32_t hsm,
        int nch, const float* __restrict__ bias, int warp, int lane)
{
    const int mg = warp >> 3, ng = warp & 7;
    const bool wl = (lane == 0);
    const int g = lane >> 3, lr = lane & 7;
    const int nbase = ng * 64 + ((g >> 1) << 3) + lr;
    const int jpar = g & 1;

    const uint32_t habase = hsm + (uint32_t)(mg * 32 + (lane & 15)) * 1040
                          + (uint32_t)((lane >> 4) << 4);
    uint32_t boff[4];
    #pragma unroll
    for (int nt4 = 0; nt4 < 4; nt4++) {
        const int nrow = nbase + nt4 * 16;
        boff[nt4] = (uint32_t)((nrow >> 1) * 128 + (nrow & 1) * 64
                   + ((jpar ^ ((nrow >> 1) & 3)) << 4));
    }

    float acc[2][8][4];
    #pragma unroll
    for (int mt = 0; mt < 2; mt++)
        #pragma unroll
        for (int nt = 0; nt < 8; nt++)
            #pragma unroll
            for (int i = 0; i < 4; i++) acc[mt][nt][i] = 0.0f;

    uint32_t A[8], B0[16], B1[16];
    uint32_t wb = slot_wait(S, S.gc);
    load_A(A, habase);
    load_B(B0, wb, boff, 0);

    #pragma unroll 1
    for (int kc = 0; kc < nch; kc++) {
        load_B(B1, wb, boff, 0x20);          // (kc, ks1)
        mma_batch(acc, A, B0);               // (kc, ks0)
        load_A(A, habase + kc * 64 + 32);    // (kc, ks1)
        uint32_t wb2 = wb;
        if (kc + 1 < nch) {
            wb2 = slot_wait(S, S.gc + 1);
            load_B(B0, wb2, boff, 0);        // (kc+1, ks0)
        }
        mma_batch(acc, A, B1);               // (kc, ks1)
        if (kc + 1 < nch) load_A(A, habase + (kc + 1) * 64);
        consume_done(S, wl);
        produce_next(S);
        wb = wb2;
    }

    __syncthreads();   // all reads of h done -> safe to overwrite in place

    #pragma unroll
    for (int mt = 0; mt < 2; mt++) {
        #pragma unroll
        for (int nt = 0; nt < 8; nt++) {
            const int cb = ng * 64 + nt * 8 + (lane & 3) * 2;
            const float2 bb = *(const float2*)(bias + cb);
            const int r0 = mg * 32 + mt * 16 + (lane >> 2);
            float v0 = tanh_fast(acc[mt][nt][0] + bb.x);
            float v1 = tanh_fast(acc[mt][nt][1] + bb.y);
            float v2 = tanh_fast(acc[mt][nt][2] + bb.x);
            float v3 = tanh_fast(acc[mt][nt][3] + bb.y);
            *(__half2*)(h + r0 * HSTR + cb)       = __floats2half2_rn(v0, v1);
            *(__half2*)(h + (r0 + 8) * HSTR + cb) = __floats2half2_rn(v2, v3);
        }
    }
    __syncthreads();   // publish new h before next layer
}

// ---------------- layer 4: N=64, K=64 chunks, fp32 out ----------------
__device__ __forceinline__ void run_pass64(Stream& S, uint32_t hsm,
        float* __restrict__ dynout,
        int nch, const float* __restrict__ bias, int warp, int lane)
{
    const int mg = warp >> 3, ng = warp & 7;
    const bool wl = (lane == 0);
    const int g = lane >> 3, lr = lane & 7;
    const uint32_t habase = hsm + (uint32_t)(mg * 32 + (lane & 15)) * 1040
                          + (uint32_t)((lane >> 4) << 4);
    const int nrow = ng * 8 + lr;

    uint32_t boff[4];
    #pragma unroll
    for (int ks = 0; ks < 4; ks++) {
        const uint32_t j = (uint32_t)(ks * 2 + (g & 1));
        boff[ks] = (uint32_t)(nrow * 128) + ((j << 4) ^ ((uint32_t)(nrow & 7) << 4));
    }

    float acc[2][4];
    #pragma unroll
    for (int mt = 0; mt < 2; mt++)
        #pragma unroll
        for (int i = 0; i < 4; i++) acc[mt][i] = 0.0f;

    #pragma unroll 1
    for (int kc = 0; kc < nch; kc++) {
        uint32_t wb = slot_wait(S, S.gc);
        #pragma unroll
        for (int ks = 0; ks < 4; ks++) {
            uint32_t a[8];
            load_A(a, habase + kc * 128 + ks * 32);
            uint32_t b0, b1;
            ldsm2a(b0, b1, wb + boff[ks]);
            mma16816(acc[0], a,     b0, b1);
            mma16816(acc[1], a + 4, b0, b1);
        }
        consume_done(S, wl);
        produce_next(S);
    }

    const int cb = ng * 8 + (lane & 3) * 2;
    const float2 bb = *(const float2*)(bias + cb);
    #pragma unroll
    for (int mt = 0; mt < 2; mt++) {
        const int r0 = mg * 32 + mt * 16 + (lane >> 2);
        float2 f01; f01.x = acc[mt][0] + bb.x; f01.y = acc[mt][1] + bb.y;
        float2 f23; f23.x = acc[mt][2] + bb.x; f23.y = acc[mt][3] + bb.y;
        *(float2*)(dynout + (size_t)r0 * D_ + cb)       = f01;
        *(float2*)(dynout + (size_t)(r0 + 8) * D_ + cb) = f23;
    }
}

// ---------------- fused per-tile, per-expert MLP kernel ----------------
__global__ __launch_bounds__(THREADS, 1)
void mlp_kernel(const float* __restrict__ x,
                const float* __restrict__ b2, const float* __restrict__ b3,
                const float* __restrict__ b4)
{
    extern __shared__ __align__(1024) char smc[];
    __half* h = (__half*)(smc + SM_H);
    const uint32_t mb = smem_u32(smc + SM_MBAR);

    const int tid  = threadIdx.x;
    const int warp = tid >> 5, lane = tid & 31;
    const int e    = blockIdx.y;
    const int row0 = blockIdx.x * BM;

    Stream S;
    S.mb = mb;
    S.bdst0 = smem_u32(smc);
    S.gp = 0; S.gc = 0;
    S.leader = (tid == 0);
    S.wbase = g_wall + (size_t)e * EBYTES;

    if (tid == 0) {
        #pragma unroll
        for (int i = 0; i < NSLOT; i++) {
            mbar_init(mb + 8 * i, 1);
            mbar_init(mb + 32 + 8 * i, 16);
        }
        asm volatile("fence.proxy.async.shared::cta;" ::: "memory");
    }
    __syncthreads();

    produce_next(S); produce_next(S); produce_next(S); produce_next(S);

    for (int idx = tid; idx < BM * 64; idx += THREADS) {
        int r = idx >> 6, c = idx & 63;
        h[r * HSTR + c] = __float2half(x[(size_t)(row0 + r) * 64 + c]);
    }
    __syncthreads();

    const uint32_t hsm = smem_u32(h);
    float* dyn = g_dyn + ((size_t)e * B_ + row0) * D_;

    run_pass512(S, h, hsm, 2,  g_b1eff + e * H_, warp, lane);
    run_pass512(S, h, hsm, 16, b2 + e * H_,      warp, lane);
    run_pass512(S, h, hsm, 16, b3 + e * H_,      warp, lane);
    run_pass64 (S, hsm, dyn, 8, b4 + e * D_,     warp, lane);
}

// ---------------- expert-weighted combine (deterministic) ----------------
__global__ void combine_k(const float* __restrict__ ew, float* __restrict__ out)
{
    int i = blockIdx.x * blockDim.x + threadIdx.x;
    int b = i >> 6;
    float s = 0.0f;
    #pragma unroll
    for (int e = 0; e < E_; e++)
        s += ew[b * E_ + e] * g_dyn[(size_t)e * B_ * D_ + i];
    out[i] = s;
}

// ---------------- launch ----------------
extern "C" void kernel_launch(void* const* d_in, const int* in_sizes, int n_in,
                              void* d_out, int out_size)
{
    const float* t  = (const float*)d_in[0];
    const float* x  = (const float*)d_in[1];
    const float* ew = (const float*)d_in[2];
    const float* om = (const float*)d_in[3];
    const float* W1 = (const float*)d_in[4];
    const float* b1 = (const float*)d_in[5];
    const float* W2 = (const float*)d_in[6];
    const float* b2 = (const float*)d_in[7];
    const float* W3 = (const float*)d_in[8];
    const float* b3 = (const float*)d_in[9];
    const float* W4 = (const float*)d_in[10];
    const float* b4 = (const float*)d_in[11];
    float* out = (float*)d_out;

    cudaFuncSetAttribute(mlp_kernel, cudaFuncAttributeMaxDynamicSharedMemorySize, SM_TOTAL);

    // launch order keeps mlp_kernel as the ncu capture target (index 3)
    conv_small<<<(262144 + E_ * H_ + 255) / 256, 256>>>(W1, W4, b1, t, om);
    conv_w23s<<<(E_ * 512 * 256) / 256, 256>>>(W2, 2);
    conv_w23s<<<(E_ * 512 * 256) / 256, 256>>>(W3, 18);

    dim3 grid(B_ / BM, E_);
    mlp_kernel<<<grid, THREADS, SM_TOTAL>>>(x, b2, b3, b4);

    combine_k<<<(B_ * D_) / 256, 256>>>(ew, out);
}

// round 12
// speedup vs baseline: 1.2647x; 1.0064x over previous
#include <cuda_runtime.h>
#include <cuda_fp16.h>
#include <cstdint>

// ---------------- problem constants ----------------
#define E_      8
#define D_      64
#define H_      512
#define B_      32768
#define IN_RAW  67
#define BM      64
#define HSTR    520           // halves; row pitch 1040 B
#define THREADS 512

// SMEM layout (bytes)
#define NSLOT     4
#define BSLOT     32768
#define SM_H      (NSLOT * BSLOT)        // 131072
#define SM_MBAR   (SM_H + 66560)         // full[4] @ +0, empty[4] @ +32
#define SM_TOTAL  (SM_MBAR + 64)

#define NCHUNKS 42            // 2 (L1) + 16 (L2) + 16 (L3) + 8 (L4)
#define EBYTES  1179648       // per-expert blob: 34*32768 + 8*8192

// ---------------- device scratch ----------------
__device__ float g_dyn[(size_t)E_ * B_ * D_];
__device__ float g_b1eff[E_ * H_];
__device__ __align__(128) char g_wall[(size_t)E_ * EBYTES];

// ---------------- low-level helpers ----------------
__device__ __forceinline__ uint32_t smem_u32(const void* p) {
    uint32_t a;
    asm("{ .reg .u64 t; cvta.to.shared.u64 t, %1; cvt.u32.u64 %0, t; }" : "=r"(a) : "l"(p));
    return a;
}
__device__ __forceinline__ void ldsm4a(uint32_t* r, uint32_t a) {
    asm volatile("ldmatrix.sync.aligned.m8n8.x4.shared.b16 {%0,%1,%2,%3}, [%4];"
        : "=r"(r[0]), "=r"(r[1]), "=r"(r[2]), "=r"(r[3]) : "r"(a));
}
__device__ __forceinline__ void ldsm2a(uint32_t& r0, uint32_t& r1, uint32_t a) {
    asm volatile("ldmatrix.sync.aligned.m8n8.x2.shared.b16 {%0,%1}, [%2];"
        : "=r"(r0), "=r"(r1) : "r"(a));
}
__device__ __forceinline__ void mma16816(float* c, const uint32_t* a, uint32_t b0, uint32_t b1) {
    asm volatile(
        "mma.sync.aligned.m16n8k16.row.col.f32.f16.f16.f32 "
        "{%0,%1,%2,%3}, {%4,%5,%6,%7}, {%8,%9}, {%0,%1,%2,%3};"
        : "+f"(c[0]), "+f"(c[1]), "+f"(c[2]), "+f"(c[3])
        : "r"(a[0]), "r"(a[1]), "r"(a[2]), "r"(a[3]), "r"(b0), "r"(b1));
}
__device__ __forceinline__ void mbar_init(uint32_t a, uint32_t c) {
    asm volatile("mbarrier.init.shared.b64 [%0], %1;" :: "r"(a), "r"(c) : "memory");
}
__device__ __forceinline__ void mbar_arrive(uint32_t a) {
    asm volatile("mbarrier.arrive.shared.b64 _, [%0];" :: "r"(a) : "memory");
}
__device__ __forceinline__ void mbar_expect_tx(uint32_t a, uint32_t bytes) {
    asm volatile("mbarrier.arrive.expect_tx.shared.b64 _, [%0], %1;" :: "r"(a), "r"(bytes) : "memory");
}
__device__ __forceinline__ void bulk_g2s(uint32_t sdst, const void* gsrc, uint32_t bytes, uint32_t mbar) {
    asm volatile(
        "cp.async.bulk.shared::cluster.global.mbarrier::complete_tx::bytes [%0], [%1], %2, [%3];"
        :: "r"(sdst), "l"(gsrc), "r"(bytes), "r"(mbar) : "memory");
}
__device__ __forceinline__ void mbar_wait(uint32_t mbar, uint32_t parity) {
    uint32_t done;
    asm volatile(
        "{ .reg .pred p; mbarrier.try_wait.parity.acquire.cta.shared::cta.b64 p, [%1], %2; selp.b32 %0, 1, 0, p; }"
        : "=r"(done) : "r"(mbar), "r"(parity) : "memory");
    if (!done) {
        asm volatile(
            "{ .reg .pred P1;\n"
            "W_%=:\n\t"
            "mbarrier.try_wait.parity.acquire.cta.shared::cta.b64 P1, [%0], %1, 0x989680;\n\t"
            "@P1 bra.uni D_%=;\n\t"
            "bra.uni W_%=;\n"
            "D_%=: }"
            :: "r"(mbar), "r"(parity) : "memory");
    }
}
__device__ __forceinline__ float tanh_fast(float x) {
    float y;
    asm("tanh.approx.f32 %0, %1;" : "=f"(y) : "f"(x));
    return y;
}

// ---------------- weight prep (into unified blob) ----------------
__global__ void conv_small(const float* __restrict__ W1, const float* __restrict__ W4,
                           const float* __restrict__ b1, const float* __restrict__ t,
                           const float* __restrict__ omega)
{
    int i = blockIdx.x * blockDim.x + threadIdx.x;
    if (i < 131072) {
        int e = i >> 14, r = i & 16383;
        int n = r >> 5, k = (r & 31) * 2;
        int kc = k >> 5, kl = k & 31, j = kl >> 3;
        size_t base = (size_t)e * EBYTES + (size_t)kc * 32768;
        uint32_t off = (uint32_t)((n >> 1) * 128 + (n & 1) * 64
                     + ((j ^ ((n >> 1) & 3)) << 4) + (kl & 7) * 2);
        const float* s = W1 + ((size_t)e * 512 + n) * IN_RAW + k;
        *(__half2*)(g_wall + base + off) = __floats2half2_rn(s[0], s[1]);
    } else if (i < 262144) {
        int jj = i - 131072;
        int e = jj >> 14, r = jj & 16383;
        int n = r >> 8, k = (r & 255) * 2;
        int kc = k >> 6, kl = k & 63;
        size_t base = (size_t)e * EBYTES + 34u * 32768 + (size_t)kc * 8192;
        uint32_t off = (uint32_t)(n * 128) + (((uint32_t)(kl * 2)) ^ ((uint32_t)(n & 7) << 4));
        const float* s = W4 + ((size_t)e * 64 + n) * 512 + k;
        *(__half2*)(g_wall + base + off) = __floats2half2_rn(s[0], s[1]);
    } else if (i < 262144 + E_ * H_) {
        int jj = i - 262144;
        int e = jj >> 9;
        float tv = t[0], om = omega[e];
        const float* w = W1 + (size_t)jj * IN_RAW;
        g_b1eff[jj] = b1[jj] + tv * w[64] + sinf(om * tv) * w[65] + cosf(om * tv) * w[66];
    }
}
__global__ void conv_w23s(const float* __restrict__ W, int cbase) {
    int i = blockIdx.x * blockDim.x + threadIdx.x;
    int e = i >> 17, r = i & 131071;
    int n = r >> 8, k = (r & 255) * 2;
    int kc = k >> 5, kl = k & 31, j = kl >> 3;
    size_t base = (size_t)e * EBYTES + (size_t)(cbase + kc) * 32768;
    uint32_t off = (uint32_t)((n >> 1) * 128 + (n & 1) * 64
                 + ((j ^ ((n >> 1) & 3)) << 4) + (kl & 7) * 2);
    const float* s = W + ((size_t)e * 512 + n) * 512 + k;
    *(__half2*)(g_wall + base + off) = __floats2half2_rn(s[0], s[1]);
}

// ---------------- 4-slot chunk ring ----------------
struct Stream {
    uint32_t mb;       // full[s] = mb+8s, empty[s] = mb+32+8s
    uint32_t bdst0;
    int gp, gc;
    bool leader;
    const char* wbase;
};
__device__ __forceinline__ void produce_next(Stream& s) {
    int i = s.gp;
    if (i >= NCHUNKS) return;
    if (s.leader) {
        int slot = i & 3;
        uint32_t off, bytes;
        if (i < 34) { off = (uint32_t)i << 15; bytes = 32768u; }
        else        { off = (34u << 15) + ((uint32_t)(i - 34) << 13); bytes = 8192u; }
        if (i >= NSLOT) mbar_wait(s.mb + 32 + 8 * slot, (uint32_t)(((i >> 2) & 1) ^ 1));
        mbar_expect_tx(s.mb + 8 * slot, bytes);
        bulk_g2s(s.bdst0 + slot * BSLOT, s.wbase + off, bytes, s.mb + 8 * slot);
    }
    s.gp++;
}
__device__ __forceinline__ uint32_t slot_wait(Stream& s, int idx) {
    int slot = idx & 3;
    mbar_wait(s.mb + 8 * slot, (uint32_t)((idx >> 2) & 1));
    return s.bdst0 + (uint32_t)slot * BSLOT;
}
// free the chunk at S.gc (once its data is in registers), refill ring
__device__ __forceinline__ void release(Stream& s, bool wl) {
    if (wl) mbar_arrive(s.mb + 32 + 8 * (s.gc & 3));
    s.gc++;
    produce_next(s);
}

// ---------------- fragment ops ----------------
__device__ __forceinline__ void load_A(uint32_t* a, uint32_t addr) {
    ldsm4a(a,     addr);
    ldsm4a(a + 4, addr + 16 * 1040);
}
__device__ __forceinline__ void load_B(uint32_t* b, uint32_t wb, const uint32_t* boff, uint32_t x) {
    ldsm4a(b,      wb + (boff[0] ^ x));
    ldsm4a(b + 4,  wb + (boff[1] ^ x));
    ldsm4a(b + 8,  wb + (boff[2] ^ x));
    ldsm4a(b + 12, wb + (boff[3] ^ x));
}
__device__ __forceinline__ void mma_batch(float (&acc)[2][8][4], const uint32_t* a, const uint32_t* b) {
    #pragma unroll
    for (int nt4 = 0; nt4 < 4; nt4++) {
        mma16816(acc[0][2 * nt4],     a,     b[4 * nt4],     b[4 * nt4 + 1]);
        mma16816(acc[1][2 * nt4],     a + 4, b[4 * nt4],     b[4 * nt4 + 1]);
        mma16816(acc[0][2 * nt4 + 1], a,     b[4 * nt4 + 2], b[4 * nt4 + 3]);
        mma16816(acc[1][2 * nt4 + 1], a + 4, b[4 * nt4 + 2], b[4 * nt4 + 3]);
    }
}

// ---------------- N=512 pass (layers 1-3): pair-processed, early release ----------------
__device__ __forceinline__ void run_pass512(Stream& S, __half* __restrict__ h, uint32_t hsm,
        int nit /* chunk pairs */, const float* __restrict__ bias, int warp, int lane)
{
    const int mg = warp >> 3, ng = warp & 7;
    const bool wl = (lane == 0);
    const int g = lane >> 3, lr = lane & 7;
    const int nbase = ng * 64 + ((g >> 1) << 3) + lr;
    const int jpar = g & 1;

    const uint32_t habase = hsm + (uint32_t)(mg * 32 + (lane & 15)) * 1040
                          + (uint32_t)((lane >> 4) << 4);
    uint32_t boff[4];
    #pragma unroll
    for (int nt4 = 0; nt4 < 4; nt4++) {
        const int nrow = nbase + nt4 * 16;
        boff[nt4] = (uint32_t)((nrow >> 1) * 128 + (nrow & 1) * 64
                   + ((jpar ^ ((nrow >> 1) & 3)) << 4));
    }

    float acc[2][8][4];
    #pragma unroll
    for (int mt = 0; mt < 2; mt++)
        #pragma unroll
        for (int nt = 0; nt < 8; nt++)
            #pragma unroll
            for (int i = 0; i < 4; i++) acc[mt][nt][i] = 0.0f;

    uint32_t A[8], B0[16], B1[16];
    uint32_t wb0 = slot_wait(S, S.gc);
    load_A(A, habase);
    load_B(B0, wb0, boff, 0);

    #pragma unroll 1
    for (int it = 0; it < nit; it++) {
        const uint32_t hb = habase + (uint32_t)it * 128;
        uint32_t wb1 = slot_wait(S, S.gc + 1);
        // chunk c0: ks0 fragments already in B0; load ks1 then FREE c0
        load_B(B1, wb0, boff, 0x20);
        release(S, wl);                         // c0 slot free; copy overlaps MMAs below
        mma_batch(acc, A, B0);                  // (c0, ks0)
        load_A(A, hb + 32);
        load_B(B0, wb1, boff, 0);               // (c1, ks0)
        mma_batch(acc, A, B1);                  // (c0, ks1)
        load_A(A, hb + 64);
        load_B(B1, wb1, boff, 0x20);            // (c1, ks1) -> c1 data all in regs
        release(S, wl);                         // FREE c1
        mma_batch(acc, A, B0);                  // (c1, ks0)
        load_A(A, hb + 96);
        uint32_t wbn = wb0;
        if (it + 1 < nit) {
            wbn = slot_wait(S, S.gc);           // c2 (gc already advanced by 2)
            load_B(B0, wbn, boff, 0);
        }
        mma_batch(acc, A, B1);                  // (c1, ks1)
        if (it + 1 < nit) load_A(A, hb + 128);
        wb0 = wbn;
    }

    __syncthreads();   // all reads of h done -> safe to overwrite in place

    #pragma unroll
    for (int mt = 0; mt < 2; mt++) {
        #pragma unroll
        for (int nt = 0; nt < 8; nt++) {
            const int cb = ng * 64 + nt * 8 + (lane & 3) * 2;
            const float2 bb = *(const float2*)(bias + cb);
            const int r0 = mg * 32 + mt * 16 + (lane >> 2);
            float v0 = tanh_fast(acc[mt][nt][0] + bb.x);
            float v1 = tanh_fast(acc[mt][nt][1] + bb.y);
            float v2 = tanh_fast(acc[mt][nt][2] + bb.x);
            float v3 = tanh_fast(acc[mt][nt][3] + bb.y);
            *(__half2*)(h + r0 * HSTR + cb)       = __floats2half2_rn(v0, v1);
            *(__half2*)(h + (r0 + 8) * HSTR + cb) = __floats2half2_rn(v2, v3);
        }
    }
    __syncthreads();   // publish new h before next layer
}

// ---------------- layer 4: N=64, early release ----------------
__device__ __forceinline__ void run_pass64(Stream& S, uint32_t hsm,
        float* __restrict__ dynout,
        int nch, const float* __restrict__ bias, int warp, int lane)
{
    const int mg = warp >> 3, ng = warp & 7;
    const bool wl = (lane == 0);
    const int g = lane >> 3, lr = lane & 7;
    const uint32_t habase = hsm + (uint32_t)(mg * 32 + (lane & 15)) * 1040
                          + (uint32_t)((lane >> 4) << 4);
    const int nrow = ng * 8 + lr;

    uint32_t boff[4];
    #pragma unroll
    for (int ks = 0; ks < 4; ks++) {
        const uint32_t j = (uint32_t)(ks * 2 + (g & 1));
        boff[ks] = (uint32_t)(nrow * 128) + ((j << 4) ^ ((uint32_t)(nrow & 7) << 4));
    }

    float acc[2][4];
    #pragma unroll
    for (int mt = 0; mt < 2; mt++)
        #pragma unroll
        for (int i = 0; i < 4; i++) acc[mt][i] = 0.0f;

    #pragma unroll 1
    for (int kc = 0; kc < nch; kc++) {
        uint32_t wb = slot_wait(S, S.gc);
        uint32_t bf[8];
        #pragma unroll
        for (int ks = 0; ks < 4; ks++)
            ldsm2a(bf[2 * ks], bf[2 * ks + 1], wb + boff[ks]);
        release(S, wl);                          // slot free before MMAs
        #pragma unroll
        for (int ks = 0; ks < 4; ks++) {
            uint32_t a[8];
            load_A(a, habase + kc * 128 + ks * 32);
            mma16816(acc[0], a,     bf[2 * ks], bf[2 * ks + 1]);
            mma16816(acc[1], a + 4, bf[2 * ks], bf[2 * ks + 1]);
        }
    }

    const int cb = ng * 8 + (lane & 3) * 2;
    const float2 bb = *(const float2*)(bias + cb);
    #pragma unroll
    for (int mt = 0; mt < 2; mt++) {
        const int r0 = mg * 32 + mt * 16 + (lane >> 2);
        float2 f01; f01.x = acc[mt][0] + bb.x; f01.y = acc[mt][1] + bb.y;
        float2 f23; f23.x = acc[mt][2] + bb.x; f23.y = acc[mt][3] + bb.y;
        *(float2*)(dynout + (size_t)r0 * D_ + cb)       = f01;
        *(float2*)(dynout + (size_t)(r0 + 8) * D_ + cb) = f23;
    }
}

// ---------------- fused per-tile, per-expert MLP kernel ----------------
__global__ __launch_bounds__(THREADS, 1)
void mlp_kernel(const float* __restrict__ x,
                const float* __restrict__ b2, const float* __restrict__ b3,
                const float* __restrict__ b4)
{
    extern __shared__ __align__(1024) char smc[];
    __half* h = (__half*)(smc + SM_H);
    const uint32_t mb = smem_u32(smc + SM_MBAR);

    const int tid  = threadIdx.x;
    const int warp = tid >> 5, lane = tid & 31;
    const int e    = blockIdx.y;
    const int row0 = blockIdx.x * BM;

    Stream S;
    S.mb = mb;
    S.bdst0 = smem_u32(smc);
    S.gp = 0; S.gc = 0;
    S.leader = (tid == 0);
    S.wbase = g_wall + (size_t)e * EBYTES;

    if (tid == 0) {
        #pragma unroll
        for (int i = 0; i < NSLOT; i++) {
            mbar_init(mb + 8 * i, 1);
            mbar_init(mb + 32 + 8 * i, 16);
        }
        asm volatile("fence.proxy.async.shared::cta;" ::: "memory");
    }
    __syncthreads();

    produce_next(S); produce_next(S); produce_next(S); produce_next(S);

    for (int idx = tid; idx < BM * 64; idx += THREADS) {
        int r = idx >> 6, c = idx & 63;
        h[r * HSTR + c] = __float2half(x[(size_t)(row0 + r) * 64 + c]);
    }
    __syncthreads();

    const uint32_t hsm = smem_u32(h);
    float* dyn = g_dyn + ((size_t)e * B_ + row0) * D_;

    run_pass512(S, h, hsm, 1, g_b1eff + e * H_, warp, lane);
    run_pass512(S, h, hsm, 8, b2 + e * H_,      warp, lane);
    run_pass512(S, h, hsm, 8, b3 + e * H_,      warp, lane);
    run_pass64 (S, hsm, dyn, 8, b4 + e * D_,    warp, lane);
}

// ---------------- expert-weighted combine (deterministic) ----------------
__global__ void combine_k(const float* __restrict__ ew, float* __restrict__ out)
{
    int i = blockIdx.x * blockDim.x + threadIdx.x;
    int b = i >> 6;
    float s = 0.0f;
    #pragma unroll
    for (int e = 0; e < E_; e++)
        s += ew[b * E_ + e] * g_dyn[(size_t)e * B_ * D_ + i];
    out[i] = s;
}

// ---------------- launch ----------------
extern "C" void kernel_launch(void* const* d_in, const int* in_sizes, int n_in,
                              void* d_out, int out_size)
{
    const float* t  = (const float*)d_in[0];
    const float* x  = (const float*)d_in[1];
    const float* ew = (const float*)d_in[2];
    const float* om = (const float*)d_in[3];
    const float* W1 = (const float*)d_in[4];
    const float* b1 = (const float*)d_in[5];
    const float* W2 = (const float*)d_in[6];
    const float* b2 = (const float*)d_in[7];
    const float* W3 = (const float*)d_in[8];
    const float* b3 = (const float*)d_in[9];
    const float* W4 = (const float*)d_in[10];
    const float* b4 = (const float*)d_in[11];
    float* out = (float*)d_out;

    cudaFuncSetAttribute(mlp_kernel, cudaFuncAttributeMaxDynamicSharedMemorySize, SM_TOTAL);

    // launch order keeps mlp_kernel as the ncu capture target (index 3)
    conv_small<<<(262144 + E_ * H_ + 255) / 256, 256>>>(W1, W4, b1, t, om);
    conv_w23s<<<(E_ * 512 * 256) / 256, 256>>>(W2, 2);
    conv_w23s<<<(E_ * 512 * 256) / 256, 256>>>(W3, 18);

    dim3 grid(B_ / BM, E_);
    mlp_kernel<<<grid, THREADS, SM_TOTAL>>>(x, b2, b3, b4);

    combine_k<<<(B_ * D_) / 256, 256>>>(ew, out);
}